// round 16
// baseline (speedup 1.0000x reference)
#include <cuda_runtime.h>
#include <cuda_fp16.h>
#include <mma.h>

using namespace nvcuda;

#define DIM 128
#define MAXN 16384
#define SLOTS 256
#define GROWS 16          // rows per GEMM block -> grid 625, ~4 blocks/SM
#define GTHREADS 256
#define HP 136            // half pitch (stage tiles)
#define FP 132            // float pitch (accumulator tile)

// ---------------- device scratch ----------------
// g_deg: zero-initialized at module load; reduce_kernel re-zeroes after each
// consumption, so every kernel_launch call sees zeros (identical work per call).
__device__ uint4 g_projh[MAXN * 16];     // proj rows, 128 x fp16
__device__ uint4 g_feath[MAXN * 16];     // feat rows, 128 x fp16
__device__ float g_pa06[MAXN];           // 0.6 * (attn . proj[v])
__device__ int   g_deg[MAXN];            // atomic cursor == degree
__device__ int   g_esrc[MAXN * SLOTS];   // bucketed src indices
__device__ unsigned g_attnh[64];         // 0.4*attn as 64 x half2

// sigmoid via MUFU.TANH
__device__ __forceinline__ float fast_sigmoid(float x) {
    float t;
    asm("tanh.approx.f32 %0, %1;" : "=f"(t) : "f"(0.5f * x));
    return fmaf(t, 0.5f, 0.5f);
}

// ---------------- GEMM via tensor cores: proj = feat @ W^T ------------------
__global__ void __launch_bounds__(GTHREADS)
gemm_kernel(const float* __restrict__ feat,
            const float* __restrict__ W,
            const float* __restrict__ attn, int n) {
    extern __shared__ char smraw[];
    __half* sW = (__half*)smraw;                       // 128 x HP halves (34.8KB)
    __half* sA = (__half*)(smraw + 128 * HP * 2);      // 16 x HP halves  (4.4KB)
    float*  sAcc = (float*)smraw;                      // 16 x FP floats (reused)
    int tid = threadIdx.x;
    int row0 = blockIdx.x * GROWS;
    int warp = tid >> 5;

    if (blockIdx.x == 0 && tid < 64) {
        __half2 h = __floats2half2_rn(0.4f * attn[2 * tid], 0.4f * attn[2 * tid + 1]);
        g_attnh[tid] = *(unsigned*)&h;
    }

    // stage W -> fp16 smem
    const float2* W2 = (const float2*)W;
    for (int idx = tid; idx < DIM * 64; idx += GTHREADS) {
        int j = idx >> 6, k2 = idx & 63;
        float2 w = W2[idx];
        ((__half2*)(sW + j * HP))[k2] = __floats2half2_rn(w.x, w.y);
    }
    // stage feat rows -> fp16 smem (+ write g_feath)
    int nrows = n - row0; if (nrows > GROWS) nrows = GROWS;
    const float2* feat2 = (const float2*)feat;
    unsigned* feath = (unsigned*)g_feath;
    for (int idx = tid; idx < GROWS * 64; idx += GTHREADS) {
        int r = idx >> 6, k2 = idx & 63;
        __half2 h = __float2half2_rn(0.f);
        if (r < nrows) {
            float2 f = feat2[(row0 + r) * 64 + k2];
            h = __floats2half2_rn(f.x, f.y);
            feath[(row0 + r) * 64 + k2] = *(unsigned*)&h;
        }
        ((__half2*)(sA + r * HP))[k2] = h;
    }
    __syncthreads();

    // warp w computes 16 rows x cols [16w, 16w+16)
    {
        wmma::fragment<wmma::accumulator, 16, 16, 16, float> acc;
        wmma::fill_fragment(acc, 0.f);
        #pragma unroll
        for (int kk = 0; kk < 8; kk++) {
            wmma::fragment<wmma::matrix_a, 16, 16, 16, __half, wmma::row_major> af;
            wmma::load_matrix_sync(af, sA + kk * 16, HP);
            wmma::fragment<wmma::matrix_b, 16, 16, 16, __half, wmma::col_major> bf;
            wmma::load_matrix_sync(bf, sW + (warp * 16) * HP + kk * 16, HP);
            wmma::mma_sync(acc, af, bf, acc);
        }
        __syncthreads();   // done reading sW/sA (sAcc aliases them)
        wmma::store_matrix_sync(sAcc + warp * 16, acc, FP, wmma::mem_row_major);
    }
    __syncthreads();

    // epilogue: 8 threads per row
    {
        int r = tid >> 3, part = tid & 7;
        if (r < nrows) {
            int rowg = row0 + r;
            const float4* base = (const float4*)(sAcc + r * FP + part * 16);
            const float4* at = ((const float4*)attn) + part * 4;
            float p = 0.f;
            uint4 packs[2];
            #pragma unroll
            for (int j = 0; j < 2; j++) {
                float4 x0 = base[2 * j], x1 = base[2 * j + 1];
                float4 a0 = at[2 * j],  a1 = at[2 * j + 1];
                p += x0.x * a0.x + x0.y * a0.y + x0.z * a0.z + x0.w * a0.w
                   + x1.x * a1.x + x1.y * a1.y + x1.z * a1.z + x1.w * a1.w;
                __half2 h0 = __floats2half2_rn(x0.x, x0.y);
                __half2 h1 = __floats2half2_rn(x0.z, x0.w);
                __half2 h2 = __floats2half2_rn(x1.x, x1.y);
                __half2 h3 = __floats2half2_rn(x1.z, x1.w);
                packs[j].x = *(unsigned*)&h0; packs[j].y = *(unsigned*)&h1;
                packs[j].z = *(unsigned*)&h2; packs[j].w = *(unsigned*)&h3;
            }
            p += __shfl_xor_sync(0xffffffffu, p, 1);
            p += __shfl_xor_sync(0xffffffffu, p, 2);
            p += __shfl_xor_sync(0xffffffffu, p, 4);
            g_projh[rowg * 16 + part * 2]     = packs[0];
            g_projh[rowg * 16 + part * 2 + 1] = packs[1];
            if (part == 0) g_pa06[rowg] = 0.6f * p;
        }
    }
}

// ---------------- single-pass bucket scatter (16 chains/thread) -------------
__global__ void scatter_kernel(const int* __restrict__ src,
                               const int* __restrict__ dst, int e) {
    int i = blockIdx.x * blockDim.x + threadIdx.x;
    int base = i * 16;
    if (base + 15 < e) {
        int4 d[4], s[4];
        #pragma unroll
        for (int b = 0; b < 4; b++) {
            d[b] = ((const int4*)dst)[i * 4 + b];
            s[b] = ((const int4*)src)[i * 4 + b];
        }
        int p[16];
        #pragma unroll
        for (int b = 0; b < 4; b++) {
            p[b*4+0] = atomicAdd(&g_deg[d[b].x], 1);
            p[b*4+1] = atomicAdd(&g_deg[d[b].y], 1);
            p[b*4+2] = atomicAdd(&g_deg[d[b].z], 1);
            p[b*4+3] = atomicAdd(&g_deg[d[b].w], 1);
        }
        #pragma unroll
        for (int b = 0; b < 4; b++) {
            if (p[b*4+0] < SLOTS) g_esrc[(d[b].x << 8) + p[b*4+0]] = s[b].x;
            if (p[b*4+1] < SLOTS) g_esrc[(d[b].y << 8) + p[b*4+1]] = s[b].y;
            if (p[b*4+2] < SLOTS) g_esrc[(d[b].z << 8) + p[b*4+2]] = s[b].z;
            if (p[b*4+3] < SLOTS) g_esrc[(d[b].w << 8) + p[b*4+3]] = s[b].w;
        }
    } else {
        for (int k = base; k < e; k++) {
            int dd = dst[k];
            int pp = atomicAdd(&g_deg[dd], 1);
            if (pp < SLOTS) g_esrc[(dd << 8) + pp] = src[k];
        }
    }
}

// ---------------- fused reduce: warp/node, 8 lanes/edge ----------------------
// attn coefficients read from smem (saves 8 regs -> 4 blocks/SM without spills).
__global__ void __launch_bounds__(256, 4)
reduce_kernel(const float* __restrict__ feat,
              const float* __restrict__ eps,
              float* __restrict__ out, int n) {
    __shared__ unsigned s_attn[64];
    if (threadIdx.x < 64) s_attn[threadIdx.x] = g_attnh[threadIdx.x];
    __syncthreads();

    int v = (blockIdx.x * blockDim.x + threadIdx.x) >> 5;
    if (v >= n) return;
    int lane = threadIdx.x & 31;
    int q = lane & 7;
    int g = lane >> 3;

    uint4 t0 = g_projh[v * 16 + q * 2];
    uint4 t1 = g_projh[v * 16 + q * 2 + 1];
    __half2 er[8] = { *(__half2*)&t0.x, *(__half2*)&t0.y, *(__half2*)&t0.z, *(__half2*)&t0.w,
                      *(__half2*)&t1.x, *(__half2*)&t1.y, *(__half2*)&t1.z, *(__half2*)&t1.w };
    float c_v = g_pa06[v];

    int deg = g_deg[v];
    if (lane == 0) g_deg[v] = 0;       // restore invariant for next call
    int cnt = deg < SLOTS ? deg : SLOTS;
    const int* row = &g_esrc[v << 8];
    const uint4* sa4 = (const uint4*)s_attn;

    const __half2 zero2 = __float2half2_rn(0.f);
    __half2 acc[8] = { zero2, zero2, zero2, zero2, zero2, zero2, zero2, zero2 };

    int iters = (cnt + 3) >> 2;
    int idx = g;
    bool valid = idx < cnt;
    int ucur = valid ? row[idx] : 0;
    uint4 e0 = g_projh[ucur * 16 + q * 2];
    uint4 e1 = g_projh[ucur * 16 + q * 2 + 1];
    float pa_u = g_pa06[ucur];

    for (int it = 0; it < iters; it++) {
        int nidx = idx + 4;
        bool nvalid = nidx < cnt;
        int nu = nvalid ? row[nidx] : 0;
        uint4 ne0 = g_projh[nu * 16 + q * 2];
        uint4 ne1 = g_projh[nu * 16 + q * 2 + 1];
        float npa = g_pa06[nu];
        uint4 f0 = g_feath[ucur * 16 + q * 2];
        uint4 f1 = g_feath[ucur * 16 + q * 2 + 1];
        uint4 au0 = sa4[q * 2];
        uint4 au1 = sa4[q * 2 + 1];

        __half2 el[8] = { *(__half2*)&e0.x, *(__half2*)&e0.y, *(__half2*)&e0.z, *(__half2*)&e0.w,
                          *(__half2*)&e1.x, *(__half2*)&e1.y, *(__half2*)&e1.z, *(__half2*)&e1.w };
        __half2 a[8]  = { *(__half2*)&au0.x, *(__half2*)&au0.y, *(__half2*)&au0.z, *(__half2*)&au0.w,
                          *(__half2*)&au1.x, *(__half2*)&au1.y, *(__half2*)&au1.z, *(__half2*)&au1.w };
        __half2 s1ab = zero2, s2 = zero2;
        #pragma unroll
        for (int c = 0; c < 8; c++) {
            __half2 x = __hadd2(el[c], er[c]);
            s1ab = __hfma2(__habs2(x), a[c], s1ab);
            s2   = __hfma2(el[c], er[c], s2);
        }
        __half2 pk = __hadd2(__lows2half2(s1ab, s2), __highs2half2(s1ab, s2));
        #pragma unroll
        for (int o = 1; o < 8; o <<= 1) {
            unsigned pku = *(unsigned*)&pk;
            unsigned ot = __shfl_xor_sync(0xffffffffu, pku, o);
            pk = __hadd2(pk, *(__half2*)&ot);
        }
        float s1 = __low2float(pk) + pa_u + c_v;
        float s2f = __high2float(pk);
        float gate = fast_sigmoid(s2f);
        float w = fast_sigmoid(s1 * gate);
        w = valid ? w : 0.f;
        __half2 w2 = __float2half2_rn(w);

        __half2 fu[8] = { *(__half2*)&f0.x, *(__half2*)&f0.y, *(__half2*)&f0.z, *(__half2*)&f0.w,
                          *(__half2*)&f1.x, *(__half2*)&f1.y, *(__half2*)&f1.z, *(__half2*)&f1.w };
        #pragma unroll
        for (int c = 0; c < 8; c++) acc[c] = __hfma2(fu[c], w2, acc[c]);

        idx = nidx; valid = nvalid; pa_u = npa; ucur = nu;
        e0 = ne0; e1 = ne1;
    }

    #pragma unroll
    for (int c = 0; c < 8; c++) {
        unsigned x = *(unsigned*)&acc[c];
        unsigned y = __shfl_xor_sync(0xffffffffu, x, 8);
        acc[c] = __hadd2(acc[c], *(__half2*)&y);
        x = *(unsigned*)&acc[c];
        y = __shfl_xor_sync(0xffffffffu, x, 16);
        acc[c] = __hadd2(acc[c], *(__half2*)&y);
    }

    if (lane < 8) {
        float invd = (deg > 0) ? (1.f / (float)deg) : 0.f;
        float ge = 1.f + eps[0];
        const float4* fv = &((const float4*)feat)[v * 32 + lane * 4];
        float4* ov = &((float4*)out)[v * 32 + lane * 4];
        #pragma unroll
        for (int j = 0; j < 4; j++) {
            float2 lo = __half22float2(acc[2 * j]);
            float2 hi = __half22float2(acc[2 * j + 1]);
            float4 f = fv[j];
            float4 o;
            o.x = ge * f.x + lo.x * invd;
            o.y = ge * f.y + lo.y * invd;
            o.z = ge * f.z + hi.x * invd;
            o.w = ge * f.w + hi.y * invd;
            ov[j] = o;
        }
    }
}

// ---------------- launcher ----------------
extern "C" void kernel_launch(void* const* d_in, const int* in_sizes, int n_in,
                              void* d_out, int out_size) {
    const float* feat = (const float*)d_in[0];
    const float* fcw  = (const float*)d_in[1];
    const float* attn = (const float*)d_in[2];
    const float* eps  = (const float*)d_in[3];
    const int*   src  = (const int*)d_in[4];
    const int*   dst  = (const int*)d_in[5];

    int n = in_sizes[0] / DIM;
    int e = in_sizes[4];

    size_t smem = (size_t)(128 * HP + GROWS * HP) * sizeof(__half);  // ~39KB
    cudaFuncSetAttribute(gemm_kernel, cudaFuncAttributeMaxDynamicSharedMemorySize, (int)smem);

    // launch 1: tensor-core GEMM (625 blocks)
    gemm_kernel<<<(n + GROWS - 1) / GROWS, GTHREADS, smem>>>(feat, fcw, attn, n);
    // launch 2: bucket scatter
    int e16 = (e + 15) / 16;
    scatter_kernel<<<(e16 + 255) / 256, 256>>>(src, dst, e);
    // launch 3: reduce (attn from smem, 4 blocks/SM)
    int red_blocks = (n * 32 + 255) / 256;
    reduce_kernel<<<red_blocks, 256>>>(feat, eps, (float*)d_out, n);

    (void)n_in; (void)out_size;
}

// round 17
// speedup vs baseline: 1.1792x; 1.1792x over previous
#include <cuda_runtime.h>
#include <cuda_fp16.h>
#include <mma.h>

using namespace nvcuda;

#define DIM 128
#define MAXN 16384
#define SLOTS 256
#define GROWS 16          // rows per GEMM block -> 625 gemm blocks
#define GTHREADS 256
#define HP 136            // half pitch (stage tiles)
#define FP 132            // float pitch (accumulator tile)

// ---------------- device scratch ----------------
// g_deg: zero-initialized at module load; reduce_kernel re-zeroes after each
// consumption, so every kernel_launch call sees zeros (identical work per call).
__device__ uint4 g_projh[MAXN * 16];     // proj rows, 128 x fp16
__device__ uint4 g_feath[MAXN * 16];     // feat rows, 128 x fp16
__device__ float g_pa06[MAXN];           // 0.6 * (attn . proj[v])
__device__ int   g_deg[MAXN];            // atomic cursor == degree
__device__ int   g_esrc[MAXN * SLOTS];   // bucketed src indices
__device__ unsigned g_attnh[64];         // 0.4*attn as 64 x half2

// sigmoid via MUFU.TANH
__device__ __forceinline__ float fast_sigmoid(float x) {
    float t;
    asm("tanh.approx.f32 %0, %1;" : "=f"(t) : "f"(0.5f * x));
    return fmaf(t, 0.5f, 0.5f);
}

// ---------------- fused GEMM (tensor cores) + bucket scatter ----------------
// blocks [0, ngemm): proj = feat @ W^T, 16 rows each, 39KB smem
// blocks [ngemm, ...): edge scatter (latency-bound; hides in gemm bubbles)
__global__ void __launch_bounds__(GTHREADS)
fused_kernel(const float* __restrict__ feat,
             const float* __restrict__ W,
             const float* __restrict__ attn,
             const int* __restrict__ src,
             const int* __restrict__ dst,
             int n, int e, int ngemm) {
    extern __shared__ char smraw[];
    int tid = threadIdx.x;

    if (blockIdx.x >= ngemm) {
        // ---------------- scatter path (16 chains/thread) ----------------
        int i = (blockIdx.x - ngemm) * GTHREADS + tid;
        int base = i * 16;
        if (base + 15 < e) {
            int4 d[4], s[4];
            #pragma unroll
            for (int b = 0; b < 4; b++) {
                d[b] = ((const int4*)dst)[i * 4 + b];
                s[b] = ((const int4*)src)[i * 4 + b];
            }
            int p[16];
            #pragma unroll
            for (int b = 0; b < 4; b++) {
                p[b*4+0] = atomicAdd(&g_deg[d[b].x], 1);
                p[b*4+1] = atomicAdd(&g_deg[d[b].y], 1);
                p[b*4+2] = atomicAdd(&g_deg[d[b].z], 1);
                p[b*4+3] = atomicAdd(&g_deg[d[b].w], 1);
            }
            #pragma unroll
            for (int b = 0; b < 4; b++) {
                if (p[b*4+0] < SLOTS) g_esrc[(d[b].x << 8) + p[b*4+0]] = s[b].x;
                if (p[b*4+1] < SLOTS) g_esrc[(d[b].y << 8) + p[b*4+1]] = s[b].y;
                if (p[b*4+2] < SLOTS) g_esrc[(d[b].z << 8) + p[b*4+2]] = s[b].z;
                if (p[b*4+3] < SLOTS) g_esrc[(d[b].w << 8) + p[b*4+3]] = s[b].w;
            }
        } else {
            for (int k = base; k < e; k++) {
                int dd = dst[k];
                int pp = atomicAdd(&g_deg[dd], 1);
                if (pp < SLOTS) g_esrc[(dd << 8) + pp] = src[k];
            }
        }
        return;
    }

    // ---------------- GEMM path ----------------
    __half* sW = (__half*)smraw;                       // 128 x HP halves (34.8KB)
    __half* sA = (__half*)(smraw + 128 * HP * 2);      // 16 x HP halves  (4.4KB)
    float*  sAcc = (float*)smraw;                      // 16 x FP floats (reused)
    int row0 = blockIdx.x * GROWS;
    int warp = tid >> 5;

    if (blockIdx.x == 0 && tid < 64) {
        __half2 h = __floats2half2_rn(0.4f * attn[2 * tid], 0.4f * attn[2 * tid + 1]);
        g_attnh[tid] = *(unsigned*)&h;
    }

    // stage W -> fp16 smem
    const float2* W2 = (const float2*)W;
    for (int idx = tid; idx < DIM * 64; idx += GTHREADS) {
        int j = idx >> 6, k2 = idx & 63;
        float2 w = W2[idx];
        ((__half2*)(sW + j * HP))[k2] = __floats2half2_rn(w.x, w.y);
    }
    // stage feat rows -> fp16 smem (+ write g_feath)
    int nrows = n - row0; if (nrows > GROWS) nrows = GROWS;
    const float2* feat2 = (const float2*)feat;
    unsigned* feath = (unsigned*)g_feath;
    for (int idx = tid; idx < GROWS * 64; idx += GTHREADS) {
        int r = idx >> 6, k2 = idx & 63;
        __half2 h = __float2half2_rn(0.f);
        if (r < nrows) {
            float2 f = feat2[(row0 + r) * 64 + k2];
            h = __floats2half2_rn(f.x, f.y);
            feath[(row0 + r) * 64 + k2] = *(unsigned*)&h;
        }
        ((__half2*)(sA + r * HP))[k2] = h;
    }
    __syncthreads();

    // warp w computes 16 rows x cols [16w, 16w+16)
    {
        wmma::fragment<wmma::accumulator, 16, 16, 16, float> acc;
        wmma::fill_fragment(acc, 0.f);
        #pragma unroll
        for (int kk = 0; kk < 8; kk++) {
            wmma::fragment<wmma::matrix_a, 16, 16, 16, __half, wmma::row_major> af;
            wmma::load_matrix_sync(af, sA + kk * 16, HP);
            wmma::fragment<wmma::matrix_b, 16, 16, 16, __half, wmma::col_major> bf;
            wmma::load_matrix_sync(bf, sW + (warp * 16) * HP + kk * 16, HP);
            wmma::mma_sync(acc, af, bf, acc);
        }
        __syncthreads();   // done reading sW/sA (sAcc aliases them)
        wmma::store_matrix_sync(sAcc + warp * 16, acc, FP, wmma::mem_row_major);
    }
    __syncthreads();

    // epilogue: 8 threads per row
    {
        int r = tid >> 3, part = tid & 7;
        if (r < nrows) {
            int rowg = row0 + r;
            const float4* base = (const float4*)(sAcc + r * FP + part * 16);
            const float4* at = ((const float4*)attn) + part * 4;
            float p = 0.f;
            uint4 packs[2];
            #pragma unroll
            for (int j = 0; j < 2; j++) {
                float4 x0 = base[2 * j], x1 = base[2 * j + 1];
                float4 a0 = at[2 * j],  a1 = at[2 * j + 1];
                p += x0.x * a0.x + x0.y * a0.y + x0.z * a0.z + x0.w * a0.w
                   + x1.x * a1.x + x1.y * a1.y + x1.z * a1.z + x1.w * a1.w;
                __half2 h0 = __floats2half2_rn(x0.x, x0.y);
                __half2 h1 = __floats2half2_rn(x0.z, x0.w);
                __half2 h2 = __floats2half2_rn(x1.x, x1.y);
                __half2 h3 = __floats2half2_rn(x1.z, x1.w);
                packs[j].x = *(unsigned*)&h0; packs[j].y = *(unsigned*)&h1;
                packs[j].z = *(unsigned*)&h2; packs[j].w = *(unsigned*)&h3;
            }
            p += __shfl_xor_sync(0xffffffffu, p, 1);
            p += __shfl_xor_sync(0xffffffffu, p, 2);
            p += __shfl_xor_sync(0xffffffffu, p, 4);
            g_projh[rowg * 16 + part * 2]     = packs[0];
            g_projh[rowg * 16 + part * 2 + 1] = packs[1];
            if (part == 0) g_pa06[rowg] = 0.6f * p;
        }
    }
}

// ---------------- fused reduce: warp/node, 8 lanes/edge (R15 exact) ----------
__global__ void __launch_bounds__(256, 3)
reduce_kernel(const float* __restrict__ feat,
              const float* __restrict__ eps,
              float* __restrict__ out, int n) {
    int v = (blockIdx.x * blockDim.x + threadIdx.x) >> 5;
    if (v >= n) return;
    int lane = threadIdx.x & 31;
    int q = lane & 7;
    int g = lane >> 3;

    uint4 t0 = g_projh[v * 16 + q * 2];
    uint4 t1 = g_projh[v * 16 + q * 2 + 1];
    __half2 er[8] = { *(__half2*)&t0.x, *(__half2*)&t0.y, *(__half2*)&t0.z, *(__half2*)&t0.w,
                      *(__half2*)&t1.x, *(__half2*)&t1.y, *(__half2*)&t1.z, *(__half2*)&t1.w };
    uint4 u0 = ((const uint4*)g_attnh)[q * 2];
    uint4 u1 = ((const uint4*)g_attnh)[q * 2 + 1];
    __half2 a[8]  = { *(__half2*)&u0.x, *(__half2*)&u0.y, *(__half2*)&u0.z, *(__half2*)&u0.w,
                      *(__half2*)&u1.x, *(__half2*)&u1.y, *(__half2*)&u1.z, *(__half2*)&u1.w };
    float c_v = g_pa06[v];

    int deg = g_deg[v];
    if (lane == 0) g_deg[v] = 0;       // restore invariant for next call
    int cnt = deg < SLOTS ? deg : SLOTS;
    const int* row = &g_esrc[v << 8];

    const __half2 zero2 = __float2half2_rn(0.f);
    __half2 acc[8] = { zero2, zero2, zero2, zero2, zero2, zero2, zero2, zero2 };

    int iters = (cnt + 3) >> 2;
    int idx = g;
    bool valid = idx < cnt;
    int ucur = valid ? row[idx] : 0;
    uint4 e0 = g_projh[ucur * 16 + q * 2];
    uint4 e1 = g_projh[ucur * 16 + q * 2 + 1];
    float pa_u = g_pa06[ucur];

    for (int it = 0; it < iters; it++) {
        int nidx = idx + 4;
        bool nvalid = nidx < cnt;
        int nu = nvalid ? row[nidx] : 0;
        uint4 ne0 = g_projh[nu * 16 + q * 2];
        uint4 ne1 = g_projh[nu * 16 + q * 2 + 1];
        float npa = g_pa06[nu];
        uint4 f0 = g_feath[ucur * 16 + q * 2];
        uint4 f1 = g_feath[ucur * 16 + q * 2 + 1];

        __half2 el[8] = { *(__half2*)&e0.x, *(__half2*)&e0.y, *(__half2*)&e0.z, *(__half2*)&e0.w,
                          *(__half2*)&e1.x, *(__half2*)&e1.y, *(__half2*)&e1.z, *(__half2*)&e1.w };
        __half2 s1ab = zero2, s2 = zero2;
        #pragma unroll
        for (int c = 0; c < 8; c++) {
            __half2 x = __hadd2(el[c], er[c]);
            s1ab = __hfma2(__habs2(x), a[c], s1ab);
            s2   = __hfma2(el[c], er[c], s2);
        }
        __half2 pk = __hadd2(__lows2half2(s1ab, s2), __highs2half2(s1ab, s2));
        #pragma unroll
        for (int o = 1; o < 8; o <<= 1) {
            unsigned pku = *(unsigned*)&pk;
            unsigned ot = __shfl_xor_sync(0xffffffffu, pku, o);
            pk = __hadd2(pk, *(__half2*)&ot);
        }
        float s1 = __low2float(pk) + pa_u + c_v;
        float s2f = __high2float(pk);
        float gate = fast_sigmoid(s2f);
        float w = fast_sigmoid(s1 * gate);
        w = valid ? w : 0.f;
        __half2 w2 = __float2half2_rn(w);

        __half2 fu[8] = { *(__half2*)&f0.x, *(__half2*)&f0.y, *(__half2*)&f0.z, *(__half2*)&f0.w,
                          *(__half2*)&f1.x, *(__half2*)&f1.y, *(__half2*)&f1.z, *(__half2*)&f1.w };
        #pragma unroll
        for (int c = 0; c < 8; c++) acc[c] = __hfma2(fu[c], w2, acc[c]);

        idx = nidx; valid = nvalid; pa_u = npa; ucur = nu;
        e0 = ne0; e1 = ne1;
    }

    #pragma unroll
    for (int c = 0; c < 8; c++) {
        unsigned x = *(unsigned*)&acc[c];
        unsigned y = __shfl_xor_sync(0xffffffffu, x, 8);
        acc[c] = __hadd2(acc[c], *(__half2*)&y);
        x = *(unsigned*)&acc[c];
        y = __shfl_xor_sync(0xffffffffu, x, 16);
        acc[c] = __hadd2(acc[c], *(__half2*)&y);
    }

    if (lane < 8) {
        float invd = (deg > 0) ? (1.f / (float)deg) : 0.f;
        float ge = 1.f + eps[0];
        const float4* fv = &((const float4*)feat)[v * 32 + lane * 4];
        float4* ov = &((float4*)out)[v * 32 + lane * 4];
        #pragma unroll
        for (int j = 0; j < 4; j++) {
            float2 lo = __half22float2(acc[2 * j]);
            float2 hi = __half22float2(acc[2 * j + 1]);
            float4 f = fv[j];
            float4 o;
            o.x = ge * f.x + lo.x * invd;
            o.y = ge * f.y + lo.y * invd;
            o.z = ge * f.z + hi.x * invd;
            o.w = ge * f.w + hi.y * invd;
            ov[j] = o;
        }
    }
}

// ---------------- launcher ----------------
extern "C" void kernel_launch(void* const* d_in, const int* in_sizes, int n_in,
                              void* d_out, int out_size) {
    const float* feat = (const float*)d_in[0];
    const float* fcw  = (const float*)d_in[1];
    const float* attn = (const float*)d_in[2];
    const float* eps  = (const float*)d_in[3];
    const int*   src  = (const int*)d_in[4];
    const int*   dst  = (const int*)d_in[5];

    int n = in_sizes[0] / DIM;
    int e = in_sizes[4];

    size_t smem = (size_t)(128 * HP + GROWS * HP) * sizeof(__half);  // ~39KB
    cudaFuncSetAttribute(fused_kernel, cudaFuncAttributeMaxDynamicSharedMemorySize, (int)smem);

    int ngemm = (n + GROWS - 1) / GROWS;          // 625
    int e16 = (e + 15) / 16;
    int nscat = (e16 + GTHREADS - 1) / GTHREADS;  // 157

    // launch 1: fused GEMM + scatter (5 blocks/SM co-residency; scatter hides
    // inside gemm latency bubbles)
    fused_kernel<<<ngemm + nscat, GTHREADS, smem>>>(feat, fcw, attn, src, dst,
                                                    n, e, ngemm);
    // launch 2: reduce (R15 exact)
    int red_blocks = (n * 32 + 255) / 256;
    reduce_kernel<<<red_blocks, 256>>>(feat, eps, (float*)d_out, n);

    (void)n_in; (void)out_size;
}